// round 6
// baseline (speedup 1.0000x reference)
#include <cuda_runtime.h>
#include <cuda_bf16.h>
#include <math.h>

// ---------------- problem constants (fixed-shape problem) ----------------
#define T_TOK 8192
#define DIM   2048
#define HID   8192
#define EPS_P 1e-4f
#define RMS_EPS 1e-5f

// ---------------- scratch (static device globals; no allocs) -------------
__device__ float g_q [(size_t)T_TOK * DIM];            // 64 MB
__device__ float g_k [(size_t)T_TOK * DIM];            // 64 MB
__device__ float g_xn[(size_t)T_TOK * DIM];            // 64 MB
__device__ float g_u [(size_t)T_TOK * 2 * HID];        // 512 MB (xn @ fc1)
__device__ float g_s [(size_t)T_TOK * HID];            // 256 MB (silu(g)*hh)
__device__ float g_z [(size_t)T_TOK * DIM];            // 64 MB
__device__ float g_nq [T_TOK];
__device__ float g_nk [T_TOK];
__device__ float g_dqk[T_TOK];
__device__ float g_a  [T_TOK];
__device__ float g_c  [T_TOK];

// ---------------- SGEMM: C[M,N] = A[M,K] @ B[K,N] (+ optional D) ----------
// 128x128 block tile, BK=8, 8x8 per thread, 256 threads, double-buffered smem.
// Requires M%128==0, N%128==0, K%8==0 (true for all shapes here).
__global__ __launch_bounds__(256, 2)
void sgemm128(const float* __restrict__ A, const float* __restrict__ B,
              const float* __restrict__ D, float* __restrict__ C,
              int M, int N, int K)
{
    __shared__ float As[2][8][128];
    __shared__ float Bs[2][8][128];

    const int tid  = threadIdx.x;
    const int trow = (tid >> 4) << 3;   // 0..120
    const int tcol = (tid & 15) << 3;   // 0..120

    const int a_row = tid >> 1;         // 0..127
    const int a_col = (tid & 1) << 2;   // 0 or 4
    const int b_row = tid >> 5;         // 0..7
    const int b_col = (tid & 31) << 2;  // 0..124

    const float* Aptr = A + (size_t)(blockIdx.y * 128 + a_row) * K + a_col;
    const float* Bptr = B + (size_t)b_row * N + (size_t)blockIdx.x * 128 + b_col;

    float acc[8][8] = {};

    // prologue: tile 0
    {
        float4 av = *(const float4*)Aptr;
        float4 bv = *(const float4*)Bptr;
        As[0][a_col + 0][a_row] = av.x;
        As[0][a_col + 1][a_row] = av.y;
        As[0][a_col + 2][a_row] = av.z;
        As[0][a_col + 3][a_row] = av.w;
        *(float4*)&Bs[0][b_row][b_col] = bv;
    }
    __syncthreads();

    int buf = 0;
    for (int kt = 8; kt <= K; kt += 8) {
        float4 av, bv;
        const bool more = (kt < K);
        if (more) {
            av = *(const float4*)(Aptr + kt);
            bv = *(const float4*)(Bptr + (size_t)kt * N);
        }
        #pragma unroll
        for (int k = 0; k < 8; ++k) {
            float4 a0 = *(const float4*)&As[buf][k][trow];
            float4 a1 = *(const float4*)&As[buf][k][trow + 4];
            float4 b0 = *(const float4*)&Bs[buf][k][tcol];
            float4 b1 = *(const float4*)&Bs[buf][k][tcol + 4];
            float af[8] = {a0.x, a0.y, a0.z, a0.w, a1.x, a1.y, a1.z, a1.w};
            float bf[8] = {b0.x, b0.y, b0.z, b0.w, b1.x, b1.y, b1.z, b1.w};
            #pragma unroll
            for (int i = 0; i < 8; ++i)
                #pragma unroll
                for (int j = 0; j < 8; ++j)
                    acc[i][j] = fmaf(af[i], bf[j], acc[i][j]);
        }
        if (more) {
            const int nb = buf ^ 1;
            As[nb][a_col + 0][a_row] = av.x;
            As[nb][a_col + 1][a_row] = av.y;
            As[nb][a_col + 2][a_row] = av.z;
            As[nb][a_col + 3][a_row] = av.w;
            *(float4*)&Bs[nb][b_row][b_col] = bv;
            __syncthreads();
            buf = nb;
        }
    }

    const size_t crow = (size_t)blockIdx.y * 128 + trow;
    const size_t ccol = (size_t)blockIdx.x * 128 + tcol;
    #pragma unroll
    for (int i = 0; i < 8; ++i) {
        size_t off = (crow + i) * (size_t)N + ccol;
        float4 v0 = make_float4(acc[i][0], acc[i][1], acc[i][2], acc[i][3]);
        float4 v1 = make_float4(acc[i][4], acc[i][5], acc[i][6], acc[i][7]);
        if (D) {
            float4 d0 = *(const float4*)(D + off);
            float4 d1 = *(const float4*)(D + off + 4);
            v0.x += d0.x; v0.y += d0.y; v0.z += d0.z; v0.w += d0.w;
            v1.x += d1.x; v1.y += d1.y; v1.z += d1.z; v1.w += d1.w;
        }
        *(float4*)(C + off)     = v0;
        *(float4*)(C + off + 4) = v1;
    }
}

// ---------------- block reduction helper ----------------
__device__ __forceinline__ float block_sum(float v, float* sm)
{
    #pragma unroll
    for (int o = 16; o > 0; o >>= 1) v += __shfl_down_sync(0xffffffffu, v, o);
    const int lane = threadIdx.x & 31, wid = threadIdx.x >> 5;
    if (lane == 0) sm[wid] = v;
    __syncthreads();
    v = (threadIdx.x < (blockDim.x >> 5)) ? sm[threadIdx.x] : 0.f;
    if (wid == 0) {
        #pragma unroll
        for (int o = 16; o > 0; o >>= 1) v += __shfl_down_sync(0xffffffffu, v, o);
    }
    return v; // valid on thread 0
}

// ---------------- rmsnorm: xn = x * rsqrt(mean(x^2)+eps) * w --------------
__global__ void rmsnorm_kernel(const float* __restrict__ x,
                               const float* __restrict__ w,
                               float* __restrict__ xn)
{
    __shared__ float sm[32];
    __shared__ float s_inv;
    const int row = blockIdx.x;
    const float* xr = x + (size_t)row * DIM;
    float ss = 0.f;
    for (int i = threadIdx.x; i < DIM; i += blockDim.x) {
        float v = xr[i];
        ss = fmaf(v, v, ss);
    }
    ss = block_sum(ss, sm);
    if (threadIdx.x == 0) s_inv = rsqrtf(ss / (float)DIM + RMS_EPS);
    __syncthreads();
    const float inv = s_inv;
    float* xo = xn + (size_t)row * DIM;
    for (int i = threadIdx.x; i < DIM; i += blockDim.x)
        xo[i] = xr[i] * inv * w[i];
}

// ------- per-token stats: |q_t|^2, |k_t|^2, q_{t-1}.k_t -------------------
__global__ void qkstats_kernel(const float* __restrict__ q,
                               const float* __restrict__ k,
                               float* __restrict__ nq2,
                               float* __restrict__ nk2,
                               float* __restrict__ dqk)
{
    __shared__ float sm[32];
    const int t = blockIdx.x;
    const float* qr = q + (size_t)t * DIM;
    const float* kr = k + (size_t)t * DIM;
    float sq = 0.f, sk = 0.f, sd = 0.f;
    for (int i = threadIdx.x; i < DIM; i += blockDim.x) {
        float qv = qr[i], kv = kr[i];
        sq = fmaf(qv, qv, sq);
        sk = fmaf(kv, kv, sk);
        if (t > 0) sd = fmaf(qr[i - DIM], kv, sd);
    }
    sq = block_sum(sq, sm);
    __syncthreads();
    sk = block_sum(sk, sm);
    __syncthreads();
    sd = block_sum(sd, sm);
    if (threadIdx.x == 0) {
        nq2[t] = sq;
        nk2[t] = sk;
        dqk[t] = (t > 0) ? sd : 0.f;
    }
}

// ------- boundary probs -> scan coefficients a_t, c_t ---------------------
__global__ void pcoef_kernel(const float* __restrict__ nq2,
                             const float* __restrict__ nk2,
                             const float* __restrict__ dqk,
                             const int* __restrict__ cu, int nseq,
                             float* __restrict__ a, float* __restrict__ c)
{
    const int t = blockIdx.x * blockDim.x + threadIdx.x;
    if (t >= T_TOK) return;
    bool ss = false;
    for (int i = 0; i < nseq; ++i) ss |= (cu[i] == t);
    float p;
    if (t == 0 || ss) {
        p = 1.0f;
    } else {
        float cosv = dqk[t] * rsqrtf(nq2[t - 1] * nk2[t]);
        p = (1.0f - cosv) * 0.5f;
    }
    p = fminf(fmaxf(p, EPS_P), 1.0f - EPS_P);
    const bool b = (p >= 0.5f);
    a[t] = (ss || t == 0) ? 0.f : (b ? 1.f - p : 1.f);
    c[t] = b ? p : 0.f;
}

// ------- SwiGLU: s = silu(u[:, h:]) * u[:, :h] ----------------------------
__global__ void swiglu_kernel(const float* __restrict__ u, float* __restrict__ s)
{
    const size_t idx = (size_t)blockIdx.x * blockDim.x + threadIdx.x; // float4 index
    const size_t total = (size_t)T_TOK * HID / 4;
    if (idx >= total) return;
    const size_t row  = idx / (HID / 4);
    const size_t col4 = idx % (HID / 4);
    const float4 hh = ((const float4*)(u + row * (size_t)(2 * HID)))[col4];
    const float4 g  = ((const float4*)(u + row * (size_t)(2 * HID) + HID))[col4];
    float4 r;
    r.x = hh.x * (g.x / (1.f + expf(-g.x)));
    r.y = hh.y * (g.y / (1.f + expf(-g.y)));
    r.z = hh.z * (g.z / (1.f + expf(-g.z)));
    r.w = hh.w * (g.w / (1.f + expf(-g.w)));
    ((float4*)s)[idx] = r;
}

// ------- segmented EMA scan: h_t = a_t h_{t-1} + c_t z_t ------------------
__global__ void ema_scan_kernel(const float* __restrict__ z,
                                const float* __restrict__ a,
                                const float* __restrict__ c,
                                const int* __restrict__ cu,
                                float* __restrict__ out)
{
    __shared__ float sa[1024];
    __shared__ float sc[1024];
    const int seg = blockIdx.y;
    const int t0 = cu[seg], t1 = cu[seg + 1];
    const int ch = blockIdx.x * blockDim.x + threadIdx.x;
    float h = 0.f;
    for (int base = t0; base < t1; base += 1024) {
        const int len = min(1024, t1 - base);
        __syncthreads();
        for (int i = threadIdx.x; i < len; i += blockDim.x) {
            sa[i] = a[base + i];
            sc[i] = c[base + i];
        }
        __syncthreads();
        for (int i = 0; i < len; ++i) {
            const size_t off = (size_t)(base + i) * DIM + ch;
            const float zv = z[off];
            h = fmaf(sa[i], h, sc[i] * zv);
            out[off] = h;
        }
    }
}

// ---------------- launch ----------------
extern "C" void kernel_launch(void* const* d_in, const int* in_sizes, int n_in,
                              void* d_out, int out_size)
{
    const float* x      = (const float*)d_in[0];
    const float* Wq     = (const float*)d_in[1];
    const float* Wk     = (const float*)d_in[2];
    const float* fc1    = (const float*)d_in[3];
    const float* fc2    = (const float*)d_in[4];
    const float* norm_w = (const float*)d_in[5];
    const int*   cu     = (const int*)d_in[6];
    float*       out    = (float*)d_out;
    const int nseq = in_sizes[6] - 1;

    float *q, *k, *xn, *u, *s, *z, *nq, *nk, *dqk, *a, *c;
    cudaGetSymbolAddress((void**)&q,   g_q);
    cudaGetSymbolAddress((void**)&k,   g_k);
    cudaGetSymbolAddress((void**)&xn,  g_xn);
    cudaGetSymbolAddress((void**)&u,   g_u);
    cudaGetSymbolAddress((void**)&s,   g_s);
    cudaGetSymbolAddress((void**)&z,   g_z);
    cudaGetSymbolAddress((void**)&nq,  g_nq);
    cudaGetSymbolAddress((void**)&nk,  g_nk);
    cudaGetSymbolAddress((void**)&dqk, g_dqk);
    cudaGetSymbolAddress((void**)&a,   g_a);
    cudaGetSymbolAddress((void**)&c,   g_c);

    // q = x @ Wq ; k = x @ Wk     [8192,2048] x [2048,2048]
    sgemm128<<<dim3(DIM / 128, T_TOK / 128), 256>>>(x, Wq, nullptr, q, T_TOK, DIM, DIM);
    sgemm128<<<dim3(DIM / 128, T_TOK / 128), 256>>>(x, Wk, nullptr, k, T_TOK, DIM, DIM);

    // boundary statistics and scan coefficients
    qkstats_kernel<<<T_TOK, 256>>>(q, k, nq, nk, dqk);
    pcoef_kernel<<<T_TOK / 256, 256>>>(nq, nk, dqk, cu, nseq, a, c);

    // xn = rmsnorm(x)
    rmsnorm_kernel<<<T_TOK, 256>>>(x, norm_w, xn);

    // u = xn @ fc1               [8192,2048] x [2048,16384]
    sgemm128<<<dim3(2 * HID / 128, T_TOK / 128), 256>>>(xn, fc1, nullptr, u, T_TOK, 2 * HID, DIM);

    // s = silu(g) * hh
    {
        const size_t total4 = (size_t)T_TOK * HID / 4;
        swiglu_kernel<<<(unsigned)((total4 + 255) / 256), 256>>>(u, s);
    }

    // z = x + s @ fc2            [8192,8192] x [8192,2048]
    sgemm128<<<dim3(DIM / 128, T_TOK / 128), 256>>>(s, fc2, x, z, T_TOK, DIM, HID);

    // segmented EMA scan -> out
    ema_scan_kernel<<<dim3(DIM / 256, nseq), 256>>>(z, a, c, cu, out);
}

// round 9
// speedup vs baseline: 2.5033x; 2.5033x over previous
#include <cuda_runtime.h>
#include <cuda_bf16.h>
#include <math.h>
#include <stdint.h>

// ---------------- problem constants (fixed-shape problem) ----------------
#define T_TOK 8192
#define DIM   2048
#define HID   8192
#define EPS_P 1e-4f
#define RMS_EPS 1e-5f

// smem tile geometry: 128 rows x 32 tf32, row stride 36 floats (conflict-free)
#define SK    36
#define TILEF 4608   // 128*36 floats per operand tile

// ---------------- scratch (static device globals; no allocs) -------------
__device__ float g_xhi [(size_t)T_TOK * DIM];
__device__ float g_xlo [(size_t)T_TOK * DIM];
__device__ float g_wqth[(size_t)DIM * DIM];
__device__ float g_wqtl[(size_t)DIM * DIM];
__device__ float g_wkth[(size_t)DIM * DIM];
__device__ float g_wktl[(size_t)DIM * DIM];
__device__ float g_fc1t[(size_t)2 * HID * DIM];
__device__ float g_fc2t[(size_t)DIM * HID];
__device__ float g_q  [(size_t)T_TOK * DIM];
__device__ float g_k  [(size_t)T_TOK * DIM];
__device__ float g_xn [(size_t)T_TOK * DIM];
__device__ float g_u  [(size_t)T_TOK * 2 * HID];
__device__ float g_s  [(size_t)T_TOK * HID];
__device__ float g_z  [(size_t)T_TOK * DIM];
__device__ float g_nq [T_TOK];
__device__ float g_nk [T_TOK];
__device__ float g_dqk[T_TOK];
__device__ float g_a  [T_TOK];
__device__ float g_c  [T_TOK];

// ---------------- PTX helpers ----------------
__device__ __forceinline__ uint32_t smem_u32(const void* p) {
    uint32_t a;
    asm("{ .reg .u64 t; cvta.to.shared.u64 t, %1; cvt.u32.u64 %0, t; }" : "=r"(a) : "l"(p));
    return a;
}
__device__ __forceinline__ float tf32_rna(float v) {
    uint32_t r;
    asm("cvt.rna.tf32.f32 %0, %1;" : "=r"(r) : "f"(v));
    return __uint_as_float(r);
}
__device__ __forceinline__ void cp16(uint32_t dst, const float* src) {
    asm volatile("cp.async.cg.shared.global [%0], [%1], 16;" :: "r"(dst), "l"(src) : "memory");
}
__device__ __forceinline__ void cp_commit() {
    asm volatile("cp.async.commit_group;" ::: "memory");
}
template<int N> __device__ __forceinline__ void cp_wait() {
    asm volatile("cp.async.wait_group %0;" :: "n"(N) : "memory");
}

// m16n8k8 row.col tf32 MMA: D += A*B, fp32 accumulate
#define MMA8(c, a, b0, b1)                                                      \
    asm volatile(                                                               \
        "mma.sync.aligned.m16n8k8.row.col.f32.tf32.tf32.f32 "                   \
        "{%0,%1,%2,%3}, {%4,%5,%6,%7}, {%8,%9}, {%0,%1,%2,%3};"                 \
        : "+f"((c)[0]), "+f"((c)[1]), "+f"((c)[2]), "+f"((c)[3])                \
        : "r"((a)[0]), "r"((a)[1]), "r"((a)[2]), "r"((a)[3]),                   \
          "r"(b0), "r"(b1))

// ---------------- TF32 mma.sync GEMM ----------------
// C[M,N] = A[M,K] @ Bt[N,K]^T (+res).  A row-major [M,K], Bt row-major [N,K].
// Operands must be tf32-rounded (rna) fp32 values.
// SPLIT: 3xTF32 hi/lo (A2/Bt2 are the lo parts).
// 256 threads, BM=BN=128, BK=32; warp grid 4(M) x 2(N), warp tile 32x64.
template<bool SPLIT, int STAGES>
__global__ __launch_bounds__(256, 1)
void gemm_mma(const float* __restrict__ A,  const float* __restrict__ A2,
              const float* __restrict__ Bt, const float* __restrict__ Bt2,
              const float* __restrict__ res, float* __restrict__ C,
              int N, int K)
{
    constexpr int NOP  = SPLIT ? 2 : 1;
    constexpr int STGF = 2 * NOP * TILEF;   // floats per pipeline stage

    extern __shared__ float sm[];
    const uint32_t sbase = smem_u32(sm);

    const int tid  = threadIdx.x;
    const int lane = tid & 31, wid = tid >> 5;
    const int warpM = wid & 3, warpN = wid >> 2;
    const int m0 = blockIdx.x * 128, n0 = blockIdx.y * 128;
    const int KT = K >> 5;

    const float* Ab  = A  + (size_t)m0 * K;
    const float* Bb  = Bt + (size_t)n0 * K;
    const float* A2b = SPLIT ? A2  + (size_t)m0 * K : nullptr;
    const float* B2b = SPLIT ? Bt2 + (size_t)n0 * K : nullptr;

    auto load_stage = [&](int s, int kt) {
        const uint32_t st = sbase + (uint32_t)s * (STGF * 4);
        const float* a = Ab + kt * 32;
        const float* b = Bb + kt * 32;
        #pragma unroll
        for (int it = 0; it < 4; ++it) {
            const int idx = tid + it * 256;
            const int r = idx >> 3, g = idx & 7;
            const uint32_t d = (uint32_t)(r * SK + g * 4) * 4;
            const size_t go = (size_t)r * K + g * 4;
            cp16(st + d, a + go);
            cp16(st + (uint32_t)(NOP * TILEF * 4) + d, b + go);
            if (SPLIT) {
                cp16(st + (uint32_t)(TILEF * 4) + d, A2b + kt * 32 + go);
                cp16(st + (uint32_t)(3 * TILEF * 4) + d, B2b + kt * 32 + go);
            }
        }
    };

    float acc[2][8][4];
    #pragma unroll
    for (int mt = 0; mt < 2; ++mt)
        #pragma unroll
        for (int nt = 0; nt < 8; ++nt)
            #pragma unroll
            for (int j = 0; j < 4; ++j) acc[mt][nt][j] = 0.f;

    // prologue
    #pragma unroll
    for (int s = 0; s < STAGES - 1; ++s) { load_stage(s, s); cp_commit(); }

    for (int kt = 0; kt < KT; ++kt) {
        __syncthreads();                       // prev compute done before overwrite
        const int lkt = kt + STAGES - 1;
        if (lkt < KT) load_stage(lkt % STAGES, lkt);
        cp_commit();
        cp_wait<STAGES - 1>();                 // stage (kt % STAGES) resident
        __syncthreads();

        const float* sA  = sm + (kt % STAGES) * STGF;
        const float* sAl = sA + TILEF;
        const float* sB  = sA + NOP * TILEF;
        const float* sBl = sB + TILEF;

        #pragma unroll
        for (int ks = 0; ks < 4; ++ks) {
            const int k0 = ks * 8 + (lane & 3);
            uint32_t aH[2][4], aL[2][4];
            #pragma unroll
            for (int mt = 0; mt < 2; ++mt) {
                const int r = warpM * 32 + mt * 16 + (lane >> 2);
                aH[mt][0] = __float_as_uint(sA[r * SK + k0]);
                aH[mt][1] = __float_as_uint(sA[(r + 8) * SK + k0]);
                aH[mt][2] = __float_as_uint(sA[r * SK + k0 + 4]);
                aH[mt][3] = __float_as_uint(sA[(r + 8) * SK + k0 + 4]);
                if (SPLIT) {
                    aL[mt][0] = __float_as_uint(sAl[r * SK + k0]);
                    aL[mt][1] = __float_as_uint(sAl[(r + 8) * SK + k0]);
                    aL[mt][2] = __float_as_uint(sAl[r * SK + k0 + 4]);
                    aL[mt][3] = __float_as_uint(sAl[(r + 8) * SK + k0 + 4]);
                }
            }
            #pragma unroll
            for (int nt = 0; nt < 8; ++nt) {
                const int n = warpN * 64 + nt * 8 + (lane >> 2);
                const uint32_t bH0 = __float_as_uint(sB[n * SK + k0]);
                const uint32_t bH1 = __float_as_uint(sB[n * SK + k0 + 4]);
                #pragma unroll
                for (int mt = 0; mt < 2; ++mt) MMA8(acc[mt][nt], aH[mt], bH0, bH1);
                if (SPLIT) {
                    const uint32_t bL0 = __float_as_uint(sBl[n * SK + k0]);
                    const uint32_t bL1 = __float_as_uint(sBl[n * SK + k0 + 4]);
                    #pragma unroll
                    for (int mt = 0; mt < 2; ++mt) {
                        MMA8(acc[mt][nt], aL[mt], bH0, bH1);   // lo*hi
                        MMA8(acc[mt][nt], aH[mt], bL0, bL1);   // hi*lo
                    }
                }
            }
        }
    }

    // epilogue
    #pragma unroll
    for (int mt = 0; mt < 2; ++mt) {
        const int r = m0 + warpM * 32 + mt * 16 + (lane >> 2);
        #pragma unroll
        for (int nt = 0; nt < 8; ++nt) {
            const int c = n0 + warpN * 64 + nt * 8 + ((lane & 3) << 1);
            float2 v0 = make_float2(acc[mt][nt][0], acc[mt][nt][1]);
            float2 v1 = make_float2(acc[mt][nt][2], acc[mt][nt][3]);
            const size_t o0 = (size_t)r * N + c;
            const size_t o1 = (size_t)(r + 8) * N + c;
            if (res) {
                const float2 d0 = *(const float2*)(res + o0);
                const float2 d1 = *(const float2*)(res + o1);
                v0.x += d0.x; v0.y += d0.y;
                v1.x += d1.x; v1.y += d1.y;
            }
            *(float2*)(C + o0) = v0;
            *(float2*)(C + o1) = v1;
        }
    }
}

// ---------------- pre-passes ----------------
__global__ void split_kernel(const float* __restrict__ x,
                             float* __restrict__ hi, float* __restrict__ lo)
{
    const size_t i = (size_t)blockIdx.x * blockDim.x + threadIdx.x;
    if (i >= (size_t)T_TOK * DIM) return;
    const float v = x[i];
    const float h = tf32_rna(v);
    hi[i] = h;
    lo[i] = tf32_rna(v - h);
}

__global__ void transpose_rna(const float* __restrict__ W, float* __restrict__ Wt,
                              int K, int N)
{
    __shared__ float t[32][33];
    const int n0 = blockIdx.x * 32, k0 = blockIdx.y * 32;
    for (int i = threadIdx.y; i < 32; i += 8)
        t[i][threadIdx.x] = W[(size_t)(k0 + i) * N + n0 + threadIdx.x];
    __syncthreads();
    for (int i = threadIdx.y; i < 32; i += 8)
        Wt[(size_t)(n0 + i) * K + k0 + threadIdx.x] = tf32_rna(t[threadIdx.x][i]);
}

__global__ void transpose_split(const float* __restrict__ W,
                                float* __restrict__ WtH, float* __restrict__ WtL,
                                int K, int N)
{
    __shared__ float t[32][33];
    const int n0 = blockIdx.x * 32, k0 = blockIdx.y * 32;
    for (int i = threadIdx.y; i < 32; i += 8)
        t[i][threadIdx.x] = W[(size_t)(k0 + i) * N + n0 + threadIdx.x];
    __syncthreads();
    for (int i = threadIdx.y; i < 32; i += 8) {
        const float v = t[threadIdx.x][i];
        const float h = tf32_rna(v);
        const size_t o = (size_t)(n0 + i) * K + k0 + threadIdx.x;
        WtH[o] = h;
        WtL[o] = tf32_rna(v - h);
    }
}

// ---------------- block reduction helper ----------------
__device__ __forceinline__ float block_sum(float v, float* sm)
{
    #pragma unroll
    for (int o = 16; o > 0; o >>= 1) v += __shfl_down_sync(0xffffffffu, v, o);
    const int lane = threadIdx.x & 31, wid = threadIdx.x >> 5;
    if (lane == 0) sm[wid] = v;
    __syncthreads();
    v = (threadIdx.x < (blockDim.x >> 5)) ? sm[threadIdx.x] : 0.f;
    if (wid == 0) {
        #pragma unroll
        for (int o = 16; o > 0; o >>= 1) v += __shfl_down_sync(0xffffffffu, v, o);
    }
    return v;
}

// ---------------- rmsnorm (emits rna-tf32 values) ----------------
__global__ void rmsnorm_kernel(const float* __restrict__ x,
                               const float* __restrict__ w,
                               float* __restrict__ xn)
{
    __shared__ float sm[32];
    __shared__ float s_inv;
    const int row = blockIdx.x;
    const float* xr = x + (size_t)row * DIM;
    float ss = 0.f;
    for (int i = threadIdx.x; i < DIM; i += blockDim.x) {
        const float v = xr[i];
        ss = fmaf(v, v, ss);
    }
    ss = block_sum(ss, sm);
    if (threadIdx.x == 0) s_inv = rsqrtf(ss / (float)DIM + RMS_EPS);
    __syncthreads();
    const float inv = s_inv;
    float* xo = xn + (size_t)row * DIM;
    for (int i = threadIdx.x; i < DIM; i += blockDim.x)
        xo[i] = tf32_rna(xr[i] * inv * w[i]);
}

// ------- per-token stats: |q_t|^2, |k_t|^2, q_{t-1}.k_t -------------------
__global__ void qkstats_kernel(const float* __restrict__ q,
                               const float* __restrict__ k,
                               float* __restrict__ nq2,
                               float* __restrict__ nk2,
                               float* __restrict__ dqk)
{
    __shared__ float sm[32];
    const int t = blockIdx.x;
    const float* qr = q + (size_t)t * DIM;
    const float* kr = k + (size_t)t * DIM;
    float sq = 0.f, sk = 0.f, sd = 0.f;
    for (int i = threadIdx.x; i < DIM; i += blockDim.x) {
        const float qv = qr[i], kv = kr[i];
        sq = fmaf(qv, qv, sq);
        sk = fmaf(kv, kv, sk);
        if (t > 0) sd = fmaf(qr[i - DIM], kv, sd);
    }
    sq = block_sum(sq, sm);
    __syncthreads();
    sk = block_sum(sk, sm);
    __syncthreads();
    sd = block_sum(sd, sm);
    if (threadIdx.x == 0) {
        nq2[t] = sq;
        nk2[t] = sk;
        dqk[t] = (t > 0) ? sd : 0.f;
    }
}

// ------- boundary probs -> scan coefficients a_t, c_t ---------------------
__global__ void pcoef_kernel(const float* __restrict__ nq2,
                             const float* __restrict__ nk2,
                             const float* __restrict__ dqk,
                             const int* __restrict__ cu, int nseq,
                             float* __restrict__ a, float* __restrict__ c)
{
    const int t = blockIdx.x * blockDim.x + threadIdx.x;
    if (t >= T_TOK) return;
    bool ss = false;
    for (int i = 0; i < nseq; ++i) ss |= (cu[i] == t);
    float p;
    if (t == 0 || ss) {
        p = 1.0f;
    } else {
        const float cosv = dqk[t] * rsqrtf(nq2[t - 1] * nk2[t]);
        p = (1.0f - cosv) * 0.5f;
    }
    p = fminf(fmaxf(p, EPS_P), 1.0f - EPS_P);
    const bool b = (p >= 0.5f);
    a[t] = (ss || t == 0) ? 0.f : (b ? 1.f - p : 1.f);
    c[t] = b ? p : 0.f;
}

// ------- SwiGLU (emits rna-tf32 values) -----------------------------------
__global__ void swiglu_kernel(const float* __restrict__ u, float* __restrict__ s)
{
    const size_t idx = (size_t)blockIdx.x * blockDim.x + threadIdx.x;
    const size_t total = (size_t)T_TOK * HID / 4;
    if (idx >= total) return;
    const size_t row  = idx / (HID / 4);
    const size_t col4 = idx % (HID / 4);
    const float4 hh = ((const float4*)(u + row * (size_t)(2 * HID)))[col4];
    const float4 g  = ((const float4*)(u + row * (size_t)(2 * HID) + HID))[col4];
    float4 r;
    r.x = tf32_rna(hh.x * (g.x / (1.f + expf(-g.x))));
    r.y = tf32_rna(hh.y * (g.y / (1.f + expf(-g.y))));
    r.z = tf32_rna(hh.z * (g.z / (1.f + expf(-g.z))));
    r.w = tf32_rna(hh.w * (g.w / (1.f + expf(-g.w))));
    ((float4*)s)[idx] = r;
}

// ------- segmented EMA scan: h_t = a_t h_{t-1} + c_t z_t ------------------
__global__ void ema_scan_kernel(const float* __restrict__ z,
                                const float* __restrict__ a,
                                const float* __restrict__ c,
                                const int* __restrict__ cu,
                                float* __restrict__ out)
{
    __shared__ float sa[1024];
    __shared__ float sc[1024];
    const int seg = blockIdx.y;
    const int t0 = cu[seg], t1 = cu[seg + 1];
    const int ch = blockIdx.x * blockDim.x + threadIdx.x;
    float h = 0.f;
    for (int base = t0; base < t1; base += 1024) {
        const int len = min(1024, t1 - base);
        __syncthreads();
        for (int i = threadIdx.x; i < len; i += blockDim.x) {
            sa[i] = a[base + i];
            sc[i] = c[base + i];
        }
        __syncthreads();
        for (int i = 0; i < len; ++i) {
            const size_t off = (size_t)(base + i) * DIM + ch;
            const float zv = z[off];
            h = fmaf(sa[i], h, sc[i] * zv);
            out[off] = h;
        }
    }
}

// ---------------- launch ----------------
extern "C" void kernel_launch(void* const* d_in, const int* in_sizes, int n_in,
                              void* d_out, int out_size)
{
    const float* x      = (const float*)d_in[0];
    const float* Wq     = (const float*)d_in[1];
    const float* Wk     = (const float*)d_in[2];
    const float* fc1    = (const float*)d_in[3];
    const float* fc2    = (const float*)d_in[4];
    const float* norm_w = (const float*)d_in[5];
    const int*   cu     = (const int*)d_in[6];
    float*       out    = (float*)d_out;
    const int nseq = in_sizes[6] - 1;

    float *xhi, *xlo, *wqth, *wqtl, *wkth, *wktl, *fc1t, *fc2t;
    float *q, *k, *xn, *u, *s, *z, *nq, *nk, *dqk, *a, *c;
    cudaGetSymbolAddress((void**)&xhi,  g_xhi);
    cudaGetSymbolAddress((void**)&xlo,  g_xlo);
    cudaGetSymbolAddress((void**)&wqth, g_wqth);
    cudaGetSymbolAddress((void**)&wqtl, g_wqtl);
    cudaGetSymbolAddress((void**)&wkth, g_wkth);
    cudaGetSymbolAddress((void**)&wktl, g_wktl);
    cudaGetSymbolAddress((void**)&fc1t, g_fc1t);
    cudaGetSymbolAddress((void**)&fc2t, g_fc2t);
    cudaGetSymbolAddress((void**)&q,    g_q);
    cudaGetSymbolAddress((void**)&k,    g_k);
    cudaGetSymbolAddress((void**)&xn,   g_xn);
    cudaGetSymbolAddress((void**)&u,    g_u);
    cudaGetSymbolAddress((void**)&s,    g_s);
    cudaGetSymbolAddress((void**)&z,    g_z);
    cudaGetSymbolAddress((void**)&nq,   g_nq);
    cudaGetSymbolAddress((void**)&nk,   g_nk);
    cudaGetSymbolAddress((void**)&dqk,  g_dqk);
    cudaGetSymbolAddress((void**)&a,    g_a);
    cudaGetSymbolAddress((void**)&c,    g_c);

    const int SMEM_PLAIN = 3 * 2 * TILEF * 4;   // 110592 B
    const int SMEM_SPLIT = 2 * 4 * TILEF * 4;   // 147456 B
    cudaFuncSetAttribute(gemm_mma<false, 3>,
                         cudaFuncAttributeMaxDynamicSharedMemorySize, SMEM_PLAIN);
    cudaFuncSetAttribute(gemm_mma<true, 2>,
                         cudaFuncAttributeMaxDynamicSharedMemorySize, SMEM_SPLIT);

    // ---- pre-passes: splits + transposed tf32 weights ----
    {
        const size_t n = (size_t)T_TOK * DIM;
        split_kernel<<<(unsigned)((n + 255) / 256), 256>>>(x, xhi, xlo);
    }
    transpose_split<<<dim3(DIM / 32, DIM / 32), dim3(32, 8)>>>(Wq, wqth, wqtl, DIM, DIM);
    transpose_split<<<dim3(DIM / 32, DIM / 32), dim3(32, 8)>>>(Wk, wkth, wktl, DIM, DIM);
    transpose_rna<<<dim3(2 * HID / 32, DIM / 32), dim3(32, 8)>>>(fc1, fc1t, DIM, 2 * HID);
    transpose_rna<<<dim3(DIM / 32, HID / 32), dim3(32, 8)>>>(fc2, fc2t, HID, DIM);

    // ---- q, k via 3xTF32 split GEMM (sign-critical path) ----
    gemm_mma<true, 2><<<dim3(T_TOK / 128, DIM / 128), 256, SMEM_SPLIT>>>(
        xhi, xlo, wqth, wqtl, nullptr, q, DIM, DIM);
    gemm_mma<true, 2><<<dim3(T_TOK / 128, DIM / 128), 256, SMEM_SPLIT>>>(
        xhi, xlo, wkth, wktl, nullptr, k, DIM, DIM);

    // boundary statistics and scan coefficients
    qkstats_kernel<<<T_TOK, 256>>>(q, k, nq, nk, dqk);
    pcoef_kernel<<<T_TOK / 256, 256>>>(nq, nk, dqk, cu, nseq, a, c);

    // xn = rmsnorm(x)  (tf32-rounded)
    rmsnorm_kernel<<<T_TOK, 256>>>(x, norm_w, xn);

    // u = xn @ fc1
    gemm_mma<false, 3><<<dim3(T_TOK / 128, 2 * HID / 128), 256, SMEM_PLAIN>>>(
        xn, nullptr, fc1t, nullptr, nullptr, u, 2 * HID, DIM);

    // s = silu(g) * hh  (tf32-rounded)
    {
        const size_t total4 = (size_t)T_TOK * HID / 4;
        swiglu_kernel<<<(unsigned)((total4 + 255) / 256), 256>>>(u, s);
    }

    // z = x + s @ fc2
    gemm_mma<false, 3><<<dim3(T_TOK / 128, DIM / 128), 256, SMEM_PLAIN>>>(
        s, nullptr, fc2t, nullptr, x, z, DIM, HID);

    // segmented EMA scan -> out
    ema_scan_kernel<<<dim3(DIM / 256, nseq), 256>>>(z, a, c, cu, out);
}

// round 10
// speedup vs baseline: 2.6888x; 1.0741x over previous
#include <cuda_runtime.h>
#include <cuda_bf16.h>
#include <math.h>
#include <stdint.h>

// ---------------- problem constants (fixed-shape problem) ----------------
#define T_TOK 8192
#define DIM   2048
#define HID   8192
#define EPS_P 1e-4f
#define RMS_EPS 1e-5f

// smem tile geometry: rows x 32 tf32, row stride 36 floats (conflict-free)
#define SK    36
#define TILEF 4608    // 128*36 floats per 128-row operand tile (old kernel)
#define STGF2 13824   // 384*36 floats per stage (new 256+128-row kernel)

// ---------------- scratch (static device globals; no allocs) -------------
__device__ float g_xhi [(size_t)T_TOK * DIM];
__device__ float g_xlo [(size_t)T_TOK * DIM];
__device__ float g_wqth[(size_t)DIM * DIM];
__device__ float g_wqtl[(size_t)DIM * DIM];
__device__ float g_wkth[(size_t)DIM * DIM];
__device__ float g_wktl[(size_t)DIM * DIM];
__device__ float g_fc1t[(size_t)2 * HID * DIM];
__device__ float g_fc2t[(size_t)DIM * HID];
__device__ float g_q  [(size_t)T_TOK * DIM];
__device__ float g_k  [(size_t)T_TOK * DIM];
__device__ float g_xn [(size_t)T_TOK * DIM];
__device__ float g_s  [(size_t)T_TOK * HID];
__device__ float g_z  [(size_t)T_TOK * DIM];
__device__ float g_nq [T_TOK];
__device__ float g_nk [T_TOK];
__device__ float g_dqk[T_TOK];
__device__ float g_a  [T_TOK];
__device__ float g_c  [T_TOK];

// ---------------- PTX helpers ----------------
__device__ __forceinline__ uint32_t smem_u32(const void* p) {
    uint32_t a;
    asm("{ .reg .u64 t; cvta.to.shared.u64 t, %1; cvt.u32.u64 %0, t; }" : "=r"(a) : "l"(p));
    return a;
}
__device__ __forceinline__ float tf32_rna(float v) {
    uint32_t r;
    asm("cvt.rna.tf32.f32 %0, %1;" : "=r"(r) : "f"(v));
    return __uint_as_float(r);
}
__device__ __forceinline__ void cp16(uint32_t dst, const float* src) {
    asm volatile("cp.async.cg.shared.global [%0], [%1], 16;" :: "r"(dst), "l"(src) : "memory");
}
__device__ __forceinline__ void cp_commit() {
    asm volatile("cp.async.commit_group;" ::: "memory");
}
template<int N> __device__ __forceinline__ void cp_wait() {
    asm volatile("cp.async.wait_group %0;" :: "n"(N) : "memory");
}

// m16n8k8 row.col tf32 MMA: D += A*B, fp32 accumulate
#define MMA8(c, a, b0, b1)                                                      \
    asm volatile(                                                               \
        "mma.sync.aligned.m16n8k8.row.col.f32.tf32.tf32.f32 "                   \
        "{%0,%1,%2,%3}, {%4,%5,%6,%7}, {%8,%9}, {%0,%1,%2,%3};"                 \
        : "+f"((c)[0]), "+f"((c)[1]), "+f"((c)[2]), "+f"((c)[3])                \
        : "r"((a)[0]), "r"((a)[1]), "r"((a)[2]), "r"((a)[3]),                   \
          "r"(b0), "r"(b1))

// ================= old 128x128 3xTF32 split GEMM (q/k path) ===============
template<bool SPLIT, int STAGES>
__global__ __launch_bounds__(256, 1)
void gemm_mma(const float* __restrict__ A,  const float* __restrict__ A2,
              const float* __restrict__ Bt, const float* __restrict__ Bt2,
              const float* __restrict__ res, float* __restrict__ C,
              int N, int K)
{
    constexpr int NOP  = SPLIT ? 2 : 1;
    constexpr int STGF = 2 * NOP * TILEF;

    extern __shared__ float sm[];
    const uint32_t sbase = smem_u32(sm);

    const int tid  = threadIdx.x;
    const int lane = tid & 31, wid = tid >> 5;
    const int warpM = wid & 3, warpN = wid >> 2;
    const int m0 = blockIdx.x * 128, n0 = blockIdx.y * 128;
    const int KT = K >> 5;

    const float* Ab  = A  + (size_t)m0 * K;
    const float* Bb  = Bt + (size_t)n0 * K;
    const float* A2b = SPLIT ? A2  + (size_t)m0 * K : nullptr;
    const float* B2b = SPLIT ? Bt2 + (size_t)n0 * K : nullptr;

    auto load_stage = [&](int s, int kt) {
        const uint32_t st = sbase + (uint32_t)s * (STGF * 4);
        const float* a = Ab + kt * 32;
        const float* b = Bb + kt * 32;
        #pragma unroll
        for (int it = 0; it < 4; ++it) {
            const int idx = tid + it * 256;
            const int r = idx >> 3, g = idx & 7;
            const uint32_t d = (uint32_t)(r * SK + g * 4) * 4;
            const size_t go = (size_t)r * K + g * 4;
            cp16(st + d, a + go);
            cp16(st + (uint32_t)(NOP * TILEF * 4) + d, b + go);
            if (SPLIT) {
                cp16(st + (uint32_t)(TILEF * 4) + d, A2b + kt * 32 + go);
                cp16(st + (uint32_t)(3 * TILEF * 4) + d, B2b + kt * 32 + go);
            }
        }
    };

    float acc[2][8][4];
    #pragma unroll
    for (int mt = 0; mt < 2; ++mt)
        #pragma unroll
        for (int nt = 0; nt < 8; ++nt)
            #pragma unroll
            for (int j = 0; j < 4; ++j) acc[mt][nt][j] = 0.f;

    #pragma unroll
    for (int s = 0; s < STAGES - 1; ++s) { load_stage(s, s); cp_commit(); }

    for (int kt = 0; kt < KT; ++kt) {
        __syncthreads();
        const int lkt = kt + STAGES - 1;
        if (lkt < KT) load_stage(lkt % STAGES, lkt);
        cp_commit();
        cp_wait<STAGES - 1>();
        __syncthreads();

        const float* sA  = sm + (kt % STAGES) * STGF;
        const float* sAl = sA + TILEF;
        const float* sB  = sA + NOP * TILEF;
        const float* sBl = sB + TILEF;

        #pragma unroll
        for (int ks = 0; ks < 4; ++ks) {
            const int k0 = ks * 8 + (lane & 3);
            uint32_t aH[2][4], aL[2][4];
            #pragma unroll
            for (int mt = 0; mt < 2; ++mt) {
                const int r = warpM * 32 + mt * 16 + (lane >> 2);
                aH[mt][0] = __float_as_uint(sA[r * SK + k0]);
                aH[mt][1] = __float_as_uint(sA[(r + 8) * SK + k0]);
                aH[mt][2] = __float_as_uint(sA[r * SK + k0 + 4]);
                aH[mt][3] = __float_as_uint(sA[(r + 8) * SK + k0 + 4]);
                if (SPLIT) {
                    aL[mt][0] = __float_as_uint(sAl[r * SK + k0]);
                    aL[mt][1] = __float_as_uint(sAl[(r + 8) * SK + k0]);
                    aL[mt][2] = __float_as_uint(sAl[r * SK + k0 + 4]);
                    aL[mt][3] = __float_as_uint(sAl[(r + 8) * SK + k0 + 4]);
                }
            }
            #pragma unroll
            for (int nt = 0; nt < 8; ++nt) {
                const int n = warpN * 64 + nt * 8 + (lane >> 2);
                const uint32_t bH0 = __float_as_uint(sB[n * SK + k0]);
                const uint32_t bH1 = __float_as_uint(sB[n * SK + k0 + 4]);
                #pragma unroll
                for (int mt = 0; mt < 2; ++mt) MMA8(acc[mt][nt], aH[mt], bH0, bH1);
                if (SPLIT) {
                    const uint32_t bL0 = __float_as_uint(sBl[n * SK + k0]);
                    const uint32_t bL1 = __float_as_uint(sBl[n * SK + k0 + 4]);
                    #pragma unroll
                    for (int mt = 0; mt < 2; ++mt) {
                        MMA8(acc[mt][nt], aL[mt], bH0, bH1);
                        MMA8(acc[mt][nt], aH[mt], bL0, bL1);
                    }
                }
            }
        }
    }

    #pragma unroll
    for (int mt = 0; mt < 2; ++mt) {
        const int r = m0 + warpM * 32 + mt * 16 + (lane >> 2);
        #pragma unroll
        for (int nt = 0; nt < 8; ++nt) {
            const int c = n0 + warpN * 64 + nt * 8 + ((lane & 3) << 1);
            float2 v0 = make_float2(acc[mt][nt][0], acc[mt][nt][1]);
            float2 v1 = make_float2(acc[mt][nt][2], acc[mt][nt][3]);
            const size_t o0 = (size_t)r * N + c;
            const size_t o1 = (size_t)(r + 8) * N + c;
            if (res) {
                const float2 d0 = *(const float2*)(res + o0);
                const float2 d1 = *(const float2*)(res + o1);
                v0.x += d0.x; v0.y += d0.y;
                v1.x += d1.x; v1.y += d1.y;
            }
            *(float2*)(C + o0) = v0;
            *(float2*)(C + o1) = v1;
        }
    }
}

// ============ new 256-row GEMM: plain (fc2+res) or fused SwiGLU (fc1) =====
// BM=256. GLU=false: BN=128, C[M,N] = A@Bt^T + res.
// GLU=true: per-half BN=64; B-halves at Bt rows [n0,n0+64) (hh) and
//           [HID+n0, HID+n0+64) (g); writes s = tf32(silu(g)*hh), N=HID.
// 256 threads, 8 warps as 4(M)x2(N); warp tile 64 rows x (64 | 2x32) cols.
template<bool GLU, int STAGES>
__global__ __launch_bounds__(256, 1)
void gemm2(const float* __restrict__ A, const float* __restrict__ Bt,
           const float* __restrict__ res, float* __restrict__ C,
           int N, int K)
{
    constexpr int NH = GLU ? 2 : 1;   // halves
    constexpr int NT = GLU ? 4 : 8;   // 8-col n-tiles per half per warp

    extern __shared__ float sm[];
    const uint32_t sbase = smem_u32(sm);

    const int tid  = threadIdx.x;
    const int lane = tid & 31, wid = tid >> 5;
    const int warpM = wid & 3, warpN = wid >> 2;
    const int m0 = blockIdx.x * 256;
    const int n0 = blockIdx.y * (GLU ? 64 : 128);
    const int KT = K >> 5;

    auto load_stage = [&](int s, int kt) {
        const uint32_t st = sbase + (uint32_t)s * (STGF2 * 4);
        #pragma unroll
        for (int it = 0; it < 12; ++it) {
            const int idx = tid + it * 256;
            const int r = idx >> 3, g = idx & 7;
            const uint32_t d = st + (uint32_t)(r * SK + g * 4) * 4;
            const float* src;
            if (r < 256) {
                src = A + (size_t)(m0 + r) * K + kt * 32 + g * 4;
            } else {
                const int rb = r - 256;
                const int brow = GLU ? ((rb < 64) ? (n0 + rb) : (HID + n0 + rb - 64))
                                     : (n0 + rb);
                src = Bt + (size_t)brow * K + kt * 32 + g * 4;
            }
            cp16(d, src);
        }
    };

    float acc[NH][4][NT][4];
    #pragma unroll
    for (int h = 0; h < NH; ++h)
        #pragma unroll
        for (int mt = 0; mt < 4; ++mt)
            #pragma unroll
            for (int nt = 0; nt < NT; ++nt)
                #pragma unroll
                for (int j = 0; j < 4; ++j) acc[h][mt][nt][j] = 0.f;

    #pragma unroll
    for (int s = 0; s < STAGES - 1; ++s) { load_stage(s, s); cp_commit(); }

    for (int kt = 0; kt < KT; ++kt) {
        __syncthreads();
        const int lkt = kt + STAGES - 1;
        if (lkt < KT) load_stage(lkt % STAGES, lkt);
        cp_commit();
        cp_wait<STAGES - 1>();
        __syncthreads();

        const float* sA = sm + (kt % STAGES) * STGF2;
        const float* sB = sA + 256 * SK;

        #pragma unroll
        for (int ks = 0; ks < 4; ++ks) {
            const int k0 = ks * 8 + (lane & 3);
            uint32_t af[4][4];
            #pragma unroll
            for (int mt = 0; mt < 4; ++mt) {
                const int r = warpM * 64 + mt * 16 + (lane >> 2);
                af[mt][0] = __float_as_uint(sA[r * SK + k0]);
                af[mt][1] = __float_as_uint(sA[(r + 8) * SK + k0]);
                af[mt][2] = __float_as_uint(sA[r * SK + k0 + 4]);
                af[mt][3] = __float_as_uint(sA[(r + 8) * SK + k0 + 4]);
            }
            #pragma unroll
            for (int h = 0; h < NH; ++h) {
                #pragma unroll
                for (int nt = 0; nt < NT; ++nt) {
                    const int n = (GLU ? (h * 64 + warpN * 32) : (warpN * 64))
                                + nt * 8 + (lane >> 2);
                    const uint32_t b0 = __float_as_uint(sB[n * SK + k0]);
                    const uint32_t b1 = __float_as_uint(sB[n * SK + k0 + 4]);
                    #pragma unroll
                    for (int mt = 0; mt < 4; ++mt)
                        MMA8(acc[h][mt][nt], af[mt], b0, b1);
                }
            }
        }
    }

    // epilogue
    #pragma unroll
    for (int mt = 0; mt < 4; ++mt) {
        const int r = m0 + warpM * 64 + mt * 16 + (lane >> 2);
        #pragma unroll
        for (int nt = 0; nt < NT; ++nt) {
            const int c = n0 + (GLU ? warpN * 32 : warpN * 64)
                        + nt * 8 + ((lane & 3) << 1);
            if (GLU) {
                #pragma unroll
                for (int j = 0; j < 2; ++j) {       // j=0: row r, j=1: row r+8
                    const size_t o = (size_t)(r + j * 8) * N + c;
                    const float hh0 = acc[0][mt][nt][2 * j];
                    const float hh1 = acc[0][mt][nt][2 * j + 1];
                    const float gg0 = acc[1][mt][nt][2 * j];
                    const float gg1 = acc[1][mt][nt][2 * j + 1];
                    float2 v;
                    v.x = tf32_rna(hh0 * (gg0 / (1.f + expf(-gg0))));
                    v.y = tf32_rna(hh1 * (gg1 / (1.f + expf(-gg1))));
                    *(float2*)(C + o) = v;
                }
            } else {
                float2 v0 = make_float2(acc[0][mt][nt][0], acc[0][mt][nt][1]);
                float2 v1 = make_float2(acc[0][mt][nt][2], acc[0][mt][nt][3]);
                const size_t o0 = (size_t)r * N + c;
                const size_t o1 = (size_t)(r + 8) * N + c;
                if (res) {
                    const float2 d0 = *(const float2*)(res + o0);
                    const float2 d1 = *(const float2*)(res + o1);
                    v0.x += d0.x; v0.y += d0.y;
                    v1.x += d1.x; v1.y += d1.y;
                }
                *(float2*)(C + o0) = v0;
                *(float2*)(C + o1) = v1;
            }
        }
    }
}

// ---------------- pre-passes ----------------
__global__ void split_kernel(const float* __restrict__ x,
                             float* __restrict__ hi, float* __restrict__ lo)
{
    const size_t i = (size_t)blockIdx.x * blockDim.x + threadIdx.x;
    if (i >= (size_t)T_TOK * DIM) return;
    const float v = x[i];
    const float h = tf32_rna(v);
    hi[i] = h;
    lo[i] = tf32_rna(v - h);
}

__global__ void transpose_rna(const float* __restrict__ W, float* __restrict__ Wt,
                              int K, int N)
{
    __shared__ float t[32][33];
    const int n0 = blockIdx.x * 32, k0 = blockIdx.y * 32;
    for (int i = threadIdx.y; i < 32; i += 8)
        t[i][threadIdx.x] = W[(size_t)(k0 + i) * N + n0 + threadIdx.x];
    __syncthreads();
    for (int i = threadIdx.y; i < 32; i += 8)
        Wt[(size_t)(n0 + i) * K + k0 + threadIdx.x] = tf32_rna(t[threadIdx.x][i]);
}

__global__ void transpose_split(const float* __restrict__ W,
                                float* __restrict__ WtH, float* __restrict__ WtL,
                                int K, int N)
{
    __shared__ float t[32][33];
    const int n0 = blockIdx.x * 32, k0 = blockIdx.y * 32;
    for (int i = threadIdx.y; i < 32; i += 8)
        t[i][threadIdx.x] = W[(size_t)(k0 + i) * N + n0 + threadIdx.x];
    __syncthreads();
    for (int i = threadIdx.y; i < 32; i += 8) {
        const float v = t[threadIdx.x][i];
        const float h = tf32_rna(v);
        const size_t o = (size_t)(n0 + i) * K + k0 + threadIdx.x;
        WtH[o] = h;
        WtL[o] = tf32_rna(v - h);
    }
}

// ---------------- block reduction helper ----------------
__device__ __forceinline__ float block_sum(float v, float* sm)
{
    #pragma unroll
    for (int o = 16; o > 0; o >>= 1) v += __shfl_down_sync(0xffffffffu, v, o);
    const int lane = threadIdx.x & 31, wid = threadIdx.x >> 5;
    if (lane == 0) sm[wid] = v;
    __syncthreads();
    v = (threadIdx.x < (blockDim.x >> 5)) ? sm[threadIdx.x] : 0.f;
    if (wid == 0) {
        #pragma unroll
        for (int o = 16; o > 0; o >>= 1) v += __shfl_down_sync(0xffffffffu, v, o);
    }
    return v;
}

// ---------------- rmsnorm (emits rna-tf32 values) ----------------
__global__ void rmsnorm_kernel(const float* __restrict__ x,
                               const float* __restrict__ w,
                               float* __restrict__ xn)
{
    __shared__ float sm[32];
    __shared__ float s_inv;
    const int row = blockIdx.x;
    const float* xr = x + (size_t)row * DIM;
    float ss = 0.f;
    for (int i = threadIdx.x; i < DIM; i += blockDim.x) {
        const float v = xr[i];
        ss = fmaf(v, v, ss);
    }
    ss = block_sum(ss, sm);
    if (threadIdx.x == 0) s_inv = rsqrtf(ss / (float)DIM + RMS_EPS);
    __syncthreads();
    const float inv = s_inv;
    float* xo = xn + (size_t)row * DIM;
    for (int i = threadIdx.x; i < DIM; i += blockDim.x)
        xo[i] = tf32_rna(xr[i] * inv * w[i]);
}

// ------- per-token stats: |q_t|^2, |k_t|^2, q_{t-1}.k_t -------------------
__global__ void qkstats_kernel(const float* __restrict__ q,
                               const float* __restrict__ k,
                               float* __restrict__ nq2,
                               float* __restrict__ nk2,
                               float* __restrict__ dqk)
{
    __shared__ float sm[32];
    const int t = blockIdx.x;
    const float* qr = q + (size_t)t * DIM;
    const float* kr = k + (size_t)t * DIM;
    float sq = 0.f, sk = 0.f, sd = 0.f;
    for (int i = threadIdx.x; i < DIM; i += blockDim.x) {
        const float qv = qr[i], kv = kr[i];
        sq = fmaf(qv, qv, sq);
        sk = fmaf(kv, kv, sk);
        if (t > 0) sd = fmaf(qr[i - DIM], kv, sd);
    }
    sq = block_sum(sq, sm);
    __syncthreads();
    sk = block_sum(sk, sm);
    __syncthreads();
    sd = block_sum(sd, sm);
    if (threadIdx.x == 0) {
        nq2[t] = sq;
        nk2[t] = sk;
        dqk[t] = (t > 0) ? sd : 0.f;
    }
}

// ------- boundary probs -> scan coefficients a_t, c_t ---------------------
__global__ void pcoef_kernel(const float* __restrict__ nq2,
                             const float* __restrict__ nk2,
                             const float* __restrict__ dqk,
                             const int* __restrict__ cu, int nseq,
                             float* __restrict__ a, float* __restrict__ c)
{
    const int t = blockIdx.x * blockDim.x + threadIdx.x;
    if (t >= T_TOK) return;
    bool ss = false;
    for (int i = 0; i < nseq; ++i) ss |= (cu[i] == t);
    float p;
    if (t == 0 || ss) {
        p = 1.0f;
    } else {
        const float cosv = dqk[t] * rsqrtf(nq2[t - 1] * nk2[t]);
        p = (1.0f - cosv) * 0.5f;
    }
    p = fminf(fmaxf(p, EPS_P), 1.0f - EPS_P);
    const bool b = (p >= 0.5f);
    a[t] = (ss || t == 0) ? 0.f : (b ? 1.f - p : 1.f);
    c[t] = b ? p : 0.f;
}

// ------- segmented EMA scan: h_t = a_t h_{t-1} + c_t z_t ------------------
__global__ void ema_scan_kernel(const float* __restrict__ z,
                                const float* __restrict__ a,
                                const float* __restrict__ c,
                                const int* __restrict__ cu,
                                float* __restrict__ out)
{
    __shared__ float sa[1024];
    __shared__ float sc[1024];
    const int seg = blockIdx.y;
    const int t0 = cu[seg], t1 = cu[seg + 1];
    const int ch = blockIdx.x * blockDim.x + threadIdx.x;
    float h = 0.f;
    for (int base = t0; base < t1; base += 1024) {
        const int len = min(1024, t1 - base);
        __syncthreads();
        for (int i = threadIdx.x; i < len; i += blockDim.x) {
            sa[i] = a[base + i];
            sc[i] = c[base + i];
        }
        __syncthreads();
        for (int i = 0; i < len; ++i) {
            const size_t off = (size_t)(base + i) * DIM + ch;
            const float zv = z[off];
            h = fmaf(sa[i], h, sc[i] * zv);
            out[off] = h;
        }
    }
}

// ---------------- launch ----------------
extern "C" void kernel_launch(void* const* d_in, const int* in_sizes, int n_in,
                              void* d_out, int out_size)
{
    const float* x      = (const float*)d_in[0];
    const float* Wq     = (const float*)d_in[1];
    const float* Wk     = (const float*)d_in[2];
    const float* fc1    = (const float*)d_in[3];
    const float* fc2    = (const float*)d_in[4];
    const float* norm_w = (const float*)d_in[5];
    const int*   cu     = (const int*)d_in[6];
    float*       out    = (float*)d_out;
    const int nseq = in_sizes[6] - 1;

    float *xhi, *xlo, *wqth, *wqtl, *wkth, *wktl, *fc1t, *fc2t;
    float *q, *k, *xn, *s, *z, *nq, *nk, *dqk, *a, *c;
    cudaGetSymbolAddress((void**)&xhi,  g_xhi);
    cudaGetSymbolAddress((void**)&xlo,  g_xlo);
    cudaGetSymbolAddress((void**)&wqth, g_wqth);
    cudaGetSymbolAddress((void**)&wqtl, g_wqtl);
    cudaGetSymbolAddress((void**)&wkth, g_wkth);
    cudaGetSymbolAddress((void**)&wktl, g_wktl);
    cudaGetSymbolAddress((void**)&fc1t, g_fc1t);
    cudaGetSymbolAddress((void**)&fc2t, g_fc2t);
    cudaGetSymbolAddress((void**)&q,    g_q);
    cudaGetSymbolAddress((void**)&k,    g_k);
    cudaGetSymbolAddress((void**)&xn,   g_xn);
    cudaGetSymbolAddress((void**)&s,    g_s);
    cudaGetSymbolAddress((void**)&z,    g_z);
    cudaGetSymbolAddress((void**)&nq,   g_nq);
    cudaGetSymbolAddress((void**)&nk,   g_nk);
    cudaGetSymbolAddress((void**)&dqk,  g_dqk);
    cudaGetSymbolAddress((void**)&a,    g_a);
    cudaGetSymbolAddress((void**)&c,    g_c);

    const int SMEM_SPLIT = 2 * 4 * TILEF * 4;   // 147456 B (old split kernel)
    const int SMEM_G2    = 3 * STGF2 * 4;       // 165888 B (new 256-row kernel)
    cudaFuncSetAttribute(gemm_mma<true, 2>,
                         cudaFuncAttributeMaxDynamicSharedMemorySize, SMEM_SPLIT);
    cudaFuncSetAttribute(gemm2<true, 3>,
                         cudaFuncAttributeMaxDynamicSharedMemorySize, SMEM_G2);
    cudaFuncSetAttribute(gemm2<false, 3>,
                         cudaFuncAttributeMaxDynamicSharedMemorySize, SMEM_G2);

    // ---- pre-passes: splits + transposed tf32 weights ----
    {
        const size_t n = (size_t)T_TOK * DIM;
        split_kernel<<<(unsigned)((n + 255) / 256), 256>>>(x, xhi, xlo);
    }
    transpose_split<<<dim3(DIM / 32, DIM / 32), dim3(32, 8)>>>(Wq, wqth, wqtl, DIM, DIM);
    transpose_split<<<dim3(DIM / 32, DIM / 32), dim3(32, 8)>>>(Wk, wkth, wktl, DIM, DIM);
    transpose_rna<<<dim3(2 * HID / 32, DIM / 32), dim3(32, 8)>>>(fc1, fc1t, DIM, 2 * HID);
    transpose_rna<<<dim3(DIM / 32, HID / 32), dim3(32, 8)>>>(fc2, fc2t, HID, DIM);

    // ---- q, k via 3xTF32 split GEMM (sign-critical path) ----
    gemm_mma<true, 2><<<dim3(T_TOK / 128, DIM / 128), 256, SMEM_SPLIT>>>(
        xhi, xlo, wqth, wqtl, nullptr, q, DIM, DIM);
    gemm_mma<true, 2><<<dim3(T_TOK / 128, DIM / 128), 256, SMEM_SPLIT>>>(
        xhi, xlo, wkth, wktl, nullptr, k, DIM, DIM);

    // boundary statistics and scan coefficients
    qkstats_kernel<<<T_TOK, 256>>>(q, k, nq, nk, dqk);
    pcoef_kernel<<<T_TOK / 256, 256>>>(nq, nk, dqk, cu, nseq, a, c);

    // xn = rmsnorm(x)  (tf32-rounded)
    rmsnorm_kernel<<<T_TOK, 256>>>(x, norm_w, xn);

    // s = silu(xn@fc1_g) * (xn@fc1_h)   -- fused fc1 + SwiGLU, no u buffer
    gemm2<true, 3><<<dim3(T_TOK / 256, HID / 64), 256, SMEM_G2>>>(
        xn, fc1t, nullptr, s, HID, DIM);

    // z = x + s @ fc2
    gemm2<false, 3><<<dim3(T_TOK / 256, DIM / 128), 256, SMEM_G2>>>(
        s, fc2t, x, z, DIM, HID);

    // segmented EMA scan -> out
    ema_scan_kernel<<<dim3(DIM / 256, nseq), 256>>>(z, a, c, cu, out);
}